// round 17
// baseline (speedup 1.0000x reference)
#include <cuda_runtime.h>
#include <cuda_bf16.h>
#include <cstdint>
#include <cstddef>
#include <math.h>

// ---------------------------------------------------------------------------
// Problem constants
// ---------------------------------------------------------------------------
#define T_SEQ   2048
#define HID     256
#define GATES   1024      // 4*HID
#define IN_DIM  22
#define D_H1    1024
#define D_H2    512
#define D_H3    1024
#define NPAIRS  65536

#define SENTINEL 0xFFFFFFFFu

// ---------------------------------------------------------------------------
// Scratch (device globals — allocation is forbidden)
// ---------------------------------------------------------------------------
__device__ float g_PRE [4 * T_SEQ * GATES];
__device__ float g_h0  [2 * T_SEQ * 512];
__device__ float g_h1  [2 * T_SEQ * 512];
__device__ float g_fc1 [2 * T_SEQ * D_H1];
__device__ float g_enc [2 * T_SEQ * D_H2];
__device__ float g_P   [2 * T_SEQ * D_H3];
__device__ float g_Ws  [D_H3 * D_H2];
__device__ float g_bs  [2 * GATES];

// ---------------------------------------------------------------------------
// Packed f32x2 helpers
// ---------------------------------------------------------------------------
#define PACK2(out, lo, hi) \
    asm("mov.b64 %0, {%1, %2};" : "=l"(out) : "f"(lo), "f"(hi))
#define UNPACK2(lo, hi, in) \
    asm("mov.b64 {%0, %1}, %2;" : "=f"(lo), "=f"(hi) : "l"(in))
#define FMA2(acc, a, b) \
    asm("fma.rn.f32x2 %0, %1, %2, %0;" : "+l"(acc) : "l"(a), "l"(b))

// ---------------------------------------------------------------------------
// Fast nonlinearities (MUFU-backed, ~1e-7 rel err)
// ---------------------------------------------------------------------------
__device__ __forceinline__ float sig_f(float x)
{
    return __fdividef(1.f, 1.f + __expf(-x));
}
__device__ __forceinline__ float tanh_f(float x)
{
    return __fdividef(2.f, 1.f + __expf(-2.f * x)) - 1.f;
}

// ---------------------------------------------------------------------------
// Re-sentinel LSTM output buffers (fallback path only)
// ---------------------------------------------------------------------------
__global__ void init_sent_kernel()
{
    unsigned idx = blockIdx.x * blockDim.x + threadIdx.x;
    const unsigned total = 2u * T_SEQ * 512u;
    if (idx < total) {
        ((unsigned*)g_h0)[idx] = SENTINEL;
        ((unsigned*)g_h1)[idx] = SENTINEL;
    }
}

// ---------------------------------------------------------------------------
// Layer-0 input gates, 16 timesteps per CTA (weights register-resident).
// grid (4, 128, 4), block 256
// ---------------------------------------------------------------------------
__global__ void __launch_bounds__(256) pre0_kernel(
    const float* __restrict__ v_r, const float* __restrict__ v_l,
    const float* __restrict__ Wih0,
    const float* __restrict__ bih0, const float* __restrict__ bhh0)
{
    const int g     = blockIdx.x * 256 + threadIdx.x;   // 0..1023
    const int tbase = blockIdx.y * 16;
    const int seq   = blockIdx.z;
    const int chain = seq >> 1, dir = seq & 1;

    __shared__ float vs[16][IN_DIM + 2];
    const float* v = (chain ? v_l : v_r) + (size_t)tbase * IN_DIM;
    for (int i = threadIdx.x; i < 16 * IN_DIM; i += 256)
        vs[i / IN_DIM][i % IN_DIM] = v[i];
    __syncthreads();

    float wr[IN_DIM];
    const float* wp = Wih0 + ((size_t)dir * GATES + g) * IN_DIM;
#pragma unroll
    for (int k = 0; k < IN_DIM; k++) wr[k] = __ldg(wp + k);
    const float b = bih0[dir * GATES + g] + bhh0[dir * GATES + g];

    float* outp = g_PRE + ((size_t)seq * T_SEQ + tbase) * GATES + g;
#pragma unroll
    for (int tt = 0; tt < 16; tt++) {
        float s = b;
#pragma unroll
        for (int k = 0; k < IN_DIM; k++) s = fmaf(wr[k], vs[tt][k], s);
        outp[(size_t)tt * GATES] = s;
    }
}

// ---------------------------------------------------------------------------
// Combined layer-1 biases / Ws = W3[:, :H2] + W3[:, H2:]
// ---------------------------------------------------------------------------
__global__ void bsum_kernel(const float* __restrict__ bih1,
                            const float* __restrict__ bhh1)
{
    int i = blockIdx.x * 256 + threadIdx.x;
    if (i < 2 * GATES) g_bs[i] = bih1[i] + bhh1[i];
}

__global__ void ws_kernel(const float* __restrict__ W3)
{
    int idx = blockIdx.x * 256 + threadIdx.x;
    if (idx < D_H3 * D_H2) {
        int i = idx >> 9;
        int j = idx & 511;
        g_Ws[idx] = W3[(size_t)i * (2 * D_H2) + j]
                  + W3[(size_t)i * (2 * D_H2) + D_H2 + j];
    }
}

// ---------------------------------------------------------------------------
// CLUSTER BiLSTM layer. grid = 64 CTAs, clusterDim = 16 (one cluster per
// sequence). CTA c owns 16 hidden units = 64 gate rows. Producers PUSH h
// into all 15 peers' smem mailboxes (mapa + st.shared::cluster) FIRST;
// consumers poll LOCAL smem, self-reset slots. Two barriers per step.
// NEW (R16): matvec in packed f32x2 — Whh pairs pre-packed in registers,
// h read as ulonglong2 (LDS.128 halves are direct FMA2 operands, no packs):
// 16 LDS.128 + 32 FFMA2 = 48 issue slots/thread vs 80 scalar.
// ---------------------------------------------------------------------------
__global__ void __launch_bounds__(256, 1) lstm_cluster_kernel(
    const float* __restrict__ PRE,    // [4][T][1024]
    const float* __restrict__ Whh,    // [2][1024][256]
    float* __restrict__ HB)           // [2][T][512]
{
    const int bx    = blockIdx.x;           // 0..63
    const int seq   = bx >> 4;              // 0..3  (cluster id)
    const int c     = bx & 15;              // chunk = cluster rank
    const int chain = seq >> 1, dir = seq & 1;
    const int tid   = threadIdx.x;
    const int rloc  = tid & 63;             // local gate row
    const int kq    = tid >> 6;             // K quarter 0..3
    const int gidx  = rloc >> 4;            // gate (i,f,g,o)
    const int jl    = rloc & 15;            // unit within chunk
    const int grow  = (gidx << 8) + (c << 4) + jl;   // global gate row

    __shared__ __align__(16) float h_s[2][256];
    __shared__ unsigned mbox[2][256];       // mailbox, sentinel protocol
    __shared__ float part[256];

    // Recurrent weights for this (row, K-quarter), packed into f32x2 pairs.
    unsigned long long w2[32];
    {
        const float* wp = Whh + ((size_t)dir * GATES + grow) * HID + kq * 64;
#pragma unroll
        for (int i = 0; i < 64; i += 4) {
            float4 v = *(const float4*)(wp + i);
            PACK2(w2[i / 2],     v.x, v.y);
            PACK2(w2[i / 2 + 1], v.z, v.w);
        }
    }

    float* hbc = HB + (size_t)chain * T_SEQ * 512;
    // Producer-side PRE base: rows (g<<8) + (c<<4) + u for u = tid
    const float* preP = PRE + (size_t)seq * T_SEQ * GATES + (c << 4) + tid;

    const bool own    = ((tid >> 4) == c);   // comp tid produced locally
    const bool isprod = (tid < 16);          // producer: unit u = tid
    float cstate = 0.f;

    const uint32_t mbox_u32 = (uint32_t)__cvta_generic_to_shared(&mbox[0][0]);
    const uint32_t mypoll   = mbox_u32 + (tid << 2);   // mbox[0][tid]

    // Peer mailbox addresses for this producer's component.
    uint32_t peerAddr[15];
    if (isprod) {
        uint32_t myaddr = mbox_u32 + (((c << 4) + tid) << 2);
#pragma unroll
        for (int p = 0; p < 15; p++) {
            int rank = p + (p >= c ? 1 : 0);
            asm("mapa.shared::cluster.u32 %0, %1, %2;"
                : "=r"(peerAddr[p]) : "r"(myaddr), "r"(rank));
        }
    }

    h_s[0][tid] = 0.f;                      // h_{-1} = 0
    h_s[1][tid] = 0.f;
    mbox[0][tid] = SENTINEL;
    mbox[1][tid] = SENTINEL;
    __syncthreads();
    asm volatile("barrier.cluster.arrive.aligned;" ::: "memory");
    asm volatile("barrier.cluster.wait.aligned;" ::: "memory");

    for (int t = 0; t < T_SEQ; t++) {
        const int t_act = dir ? (T_SEQ - 1 - t) : t;
        const int par   = t & 1;

        // Producer-side input-gate prefetch (4 rows; overlaps the poll)
        float pv[4];
        if (isprod) {
            const float* pp = preP + (size_t)t_act * GATES;
#pragma unroll
            for (int g2 = 0; g2 < 4; g2++)
                pv[g2] = __ldg(pp + (g2 << 8));
        }

        if (t > 0 && !own) {
            const uint32_t a = mypoll + (par << 10);
            unsigned v;
            do {
                asm volatile("ld.volatile.shared.u32 %0, [%1];"
                             : "=r"(v) : "r"(a));
            } while (v == SENTINEL);
            asm volatile("st.shared.u32 [%0], %1;" :: "r"(a), "r"(SENTINEL));
            h_s[par][tid] = __uint_as_float(v);
        }
        __syncthreads();                    // bar1: h_s[par] complete

        // 64-MAC partial matvec in packed f32x2 (16 LDS.128 + 32 FFMA2)
        const ulonglong2* hp2 =
            (const ulonglong2*)&h_s[par][kq << 6];
        unsigned long long a0 = 0ULL, a1 = 0ULL, a2 = 0ULL, a3 = 0ULL;
#pragma unroll
        for (int i = 0; i < 16; i += 2) {
            ulonglong2 hv0 = hp2[i];
            ulonglong2 hv1 = hp2[i + 1];
            FMA2(a0, w2[2 * i],     hv0.x);
            FMA2(a1, w2[2 * i + 1], hv0.y);
            FMA2(a2, w2[2 * i + 2], hv1.x);
            FMA2(a3, w2[2 * i + 3], hv1.y);
        }
        {
            float l0, h0, l1, h1, l2, h2, l3, h3;
            UNPACK2(l0, h0, a0);
            UNPACK2(l1, h1, a1);
            UNPACK2(l2, h2, a2);
            UNPACK2(l3, h3, a3);
            part[tid] = ((l0 + h0) + (l1 + h1)) + ((l2 + h2) + (l3 + h3));
        }
        __syncthreads();                    // bar2: part[] complete

        if (isprod) {
            // Gather 16 partials: row (g<<4)+tid, K-quarter kq2
            float gi = pv[0], gf = pv[1], gg = pv[2], go = pv[3];
#pragma unroll
            for (int kq2 = 0; kq2 < 4; kq2++) {
                const int b = (kq2 << 6) + tid;
                gi += part[b];
                gf += part[b + 16];
                gg += part[b + 32];
                go += part[b + 48];
            }
            cstate = sig_f(gf) * cstate + sig_f(gi) * tanh_f(gg);
            float h = sig_f(go) * tanh_f(cstate);
            unsigned hv = __float_as_uint(h);
            // PUSH FIRST — DSMEM landing gates every consumer's next step.
            if (t < T_SEQ - 1) {
                const uint32_t off = (unsigned)(par ^ 1) << 10;
#pragma unroll
                for (int p = 0; p < 15; p++)
                    asm volatile("st.shared::cluster.u32 [%0], %1;"
                                 :: "r"(peerAddr[p] + off), "r"(hv));
            }
            h_s[par ^ 1][(c << 4) + tid] = h;          // own comp, next step
            hbc[(size_t)t_act * 512 + dir * 256 + (c << 4) + tid] = h;
        }
        // no bar3: part[] is only overwritten after next step's bar1,
        // which producers reach only after reading part[] above.
    }
}

// ---------------------------------------------------------------------------
// FALLBACK BiLSTM layer (R9 exact): L2 sentinel polling, grid 64, block 256.
// ---------------------------------------------------------------------------
__global__ void __launch_bounds__(256, 1) lstm_kernel(
    const float* __restrict__ PRE,
    const float* __restrict__ Whh,
    float* __restrict__ HB)           // sentinel-initialized
{
    const int bx    = blockIdx.x;
    const int seq   = bx >> 4;
    const int c     = bx & 15;
    const int chain = seq >> 1, dir = seq & 1;
    const int tid   = threadIdx.x;
    const int rloc  = tid & 63;
    const int kq    = tid >> 6;
    const int gidx  = rloc >> 4;
    const int jl    = rloc & 15;
    const int grow  = (gidx << 8) + (c << 4) + jl;

    __shared__ __align__(16) float h_s[256];
    __shared__ float part[256];
    __shared__ float gate_s[64];

    float w[64];
    {
        const float* wp = Whh + ((size_t)dir * GATES + grow) * HID + kq * 64;
#pragma unroll
        for (int i = 0; i < 64; i += 4) {
            float4 v = *(const float4*)(wp + i);
            w[i] = v.x; w[i + 1] = v.y; w[i + 2] = v.z; w[i + 3] = v.w;
        }
    }

    float* hbc = HB + (size_t)chain * T_SEQ * 512;
    const float* prebase = PRE + (size_t)seq * T_SEQ * GATES + grow;
    const int  col = dir * 256 + tid;
    const bool own = ((tid >> 4) == c);
    float cstate = 0.f;

    h_s[tid] = 0.f;
    __syncthreads();

    for (int t = 0; t < T_SEQ; t++) {
        const int t_act = dir ? (T_SEQ - 1 - t) : t;

        float preval = 0.f;
        if (tid < 64)
            preval = __ldg(prebase + (size_t)t_act * GATES);

        if (t > 0 && !own) {
            const int p_act = dir ? (t_act + 1) : (t_act - 1);
            const unsigned* pp =
                (const unsigned*)(hbc + (size_t)p_act * 512 + col);
            unsigned v;
            do {
                asm volatile("ld.volatile.global.u32 %0, [%1];"
                             : "=r"(v) : "l"(pp));
            } while (v == SENTINEL);
            h_s[tid] = __uint_as_float(v);
        }
        __syncthreads();

        const float* hp = h_s + (kq << 6);
        float a0 = 0.f, a1 = 0.f, a2 = 0.f, a3 = 0.f;
#pragma unroll
        for (int i = 0; i < 64; i += 4) {
            float4 hv = *(const float4*)(hp + i);
            a0 = fmaf(w[i],     hv.x, a0);
            a1 = fmaf(w[i + 1], hv.y, a1);
            a2 = fmaf(w[i + 2], hv.z, a2);
            a3 = fmaf(w[i + 3], hv.w, a3);
        }
        part[tid] = (a0 + a1) + (a2 + a3);
        __syncthreads();

        if (tid < 64)
            gate_s[tid] = preval + part[tid] + part[tid + 64]
                        + part[tid + 128] + part[tid + 192];
        __syncthreads();

        if (tid < 16) {
            float gi = gate_s[tid];
            float gf = gate_s[16 + tid];
            float gg = gate_s[32 + tid];
            float go = gate_s[48 + tid];
            cstate = sig_f(gf) * cstate + sig_f(gi) * tanh_f(gg);
            float h = sig_f(go) * tanh_f(cstate);
            h_s[(c << 4) + tid] = h;
            unsigned hv = __float_as_uint(h);
            unsigned* dst = (unsigned*)(hbc + (size_t)t_act * 512
                                        + dir * 256 + (c << 4) + tid);
            asm volatile("st.volatile.global.u32 [%0], %1;" :: "l"(dst), "r"(hv));
        }
        __syncthreads();
    }
}

// ---------------------------------------------------------------------------
// SGEMM: C = act( alpha * ( A[M,K] @ B[N,K]^T + bias[N] ) )
// 128x128 tile, BK=8, 256 threads, 8x8 microtile, double-buffered smem,
// packed f32x2 inner product. R16: B fragments read as ulonglong2 (halves
// are direct FMA2 operands) — removes 4 PACK2 per kk.
// ---------------------------------------------------------------------------
__global__ void __launch_bounds__(256, 2) gemm_kernel(
    const float* __restrict__ A, const float* __restrict__ B,
    const float* __restrict__ bias, float* __restrict__ C,
    int M, int N, int K, float alpha, int relu,
    long sA, long sB, long sBias, long sC, int aDiv, int bMod)
{
    A    += (size_t)(blockIdx.z / aDiv) * sA;
    B    += (size_t)(blockIdx.z % bMod) * sB;
    bias += (size_t)(blockIdx.z % bMod) * sBias;
    C    += (size_t)blockIdx.z * sC;

    __shared__ __align__(16) float As[2][8][132];
    __shared__ __align__(16) float Bs[2][8][132];

    const int tid = threadIdx.x;
    const int tx = tid & 15, ty = tid >> 4;
    const int m0 = blockIdx.y * 128, n0 = blockIdx.x * 128;
    const int lrow = tid >> 1;
    const int lk   = (tid & 1) << 2;

    unsigned long long acc2[8][4];
#pragma unroll
    for (int i = 0; i < 8; i++)
#pragma unroll
        for (int p = 0; p < 4; p++) acc2[i][p] = 0ULL;

    const float* Ap = A + (size_t)(m0 + lrow) * K + lk;
    const float* Bp = B + (size_t)(n0 + lrow) * K + lk;

    // Prologue: load tile 0 into stage 0
    {
        float4 av = *(const float4*)(Ap);
        float4 bv = *(const float4*)(Bp);
        As[0][lk + 0][lrow] = av.x; As[0][lk + 1][lrow] = av.y;
        As[0][lk + 2][lrow] = av.z; As[0][lk + 3][lrow] = av.w;
        Bs[0][lk + 0][lrow] = bv.x; Bs[0][lk + 1][lrow] = bv.y;
        Bs[0][lk + 2][lrow] = bv.z; Bs[0][lk + 3][lrow] = bv.w;
    }
    __syncthreads();

    int s = 0;
    for (int k0 = 0; k0 < K; k0 += 8) {
        float4 av, bv;
        const bool more = (k0 + 8 < K);
        if (more) {
            av = *(const float4*)(Ap + k0 + 8);
            bv = *(const float4*)(Bp + k0 + 8);
        }

#pragma unroll
        for (int kk = 0; kk < 8; kk++) {
            float4 va0 = *(const float4*)&As[s][kk][tx << 2];
            float4 va1 = *(const float4*)&As[s][kk][64 + (tx << 2)];
            ulonglong2 vb0 = *(const ulonglong2*)&Bs[s][kk][ty << 2];
            ulonglong2 vb1 = *(const ulonglong2*)&Bs[s][kk][64 + (ty << 2)];
            float ar[8] = {va0.x, va0.y, va0.z, va0.w,
                           va1.x, va1.y, va1.z, va1.w};
#pragma unroll
            for (int i = 0; i < 8; i++) {
                unsigned long long aa;
                PACK2(aa, ar[i], ar[i]);
                FMA2(acc2[i][0], aa, vb0.x);
                FMA2(acc2[i][1], aa, vb0.y);
                FMA2(acc2[i][2], aa, vb1.x);
                FMA2(acc2[i][3], aa, vb1.y);
            }
        }

        if (more) {
            const int d = s ^ 1;
            As[d][lk + 0][lrow] = av.x; As[d][lk + 1][lrow] = av.y;
            As[d][lk + 2][lrow] = av.z; As[d][lk + 3][lrow] = av.w;
            Bs[d][lk + 0][lrow] = bv.x; Bs[d][lk + 1][lrow] = bv.y;
            Bs[d][lk + 2][lrow] = bv.z; Bs[d][lk + 3][lrow] = bv.w;
        }
        __syncthreads();
        s ^= 1;
    }

    float bia[8];
#pragma unroll
    for (int j = 0; j < 8; j++) {
        int n = n0 + ((j < 4) ? (ty << 2) + j : 64 + (ty << 2) + (j - 4));
        bia[j] = bias[n];
    }

#pragma unroll
    for (int i = 0; i < 8; i++) {
        int m = m0 + ((i < 4) ? (tx << 2) + i : 64 + (tx << 2) + (i - 4));
        float v[8];
#pragma unroll
        for (int p = 0; p < 4; p++) {
            float lo, hi;
            UNPACK2(lo, hi, acc2[i][p]);
            v[2 * p]     = lo;
            v[2 * p + 1] = hi;
        }
#pragma unroll
        for (int j = 0; j < 8; j++) {
            float x = alpha * (v[j] + bia[j]);
            v[j] = relu ? fmaxf(x, 0.f) : x;
        }
        float4 o0 = {v[0], v[1], v[2], v[3]};
        float4 o1 = {v[4], v[5], v[6], v[7]};
        *(float4*)(C + (size_t)m * N + n0 + (ty << 2))      = o0;
        *(float4*)(C + (size_t)m * N + n0 + 64 + (ty << 2)) = o1;
    }
}

// ---------------------------------------------------------------------------
// Pair stage: logits[p] = relu(P_r[pr] + P_l[pl]) . Wout^T + bout; log_softmax
// ---------------------------------------------------------------------------
__global__ void __launch_bounds__(256) pair_kernel(
    const int* __restrict__ pair_r, const int* __restrict__ pair_l,
    const float* __restrict__ Wout, const float* __restrict__ bout,
    float* __restrict__ out)
{
    __shared__ float w0[D_H3], w1[D_H3];
    for (int i = threadIdx.x; i < D_H3; i += 256) {
        w0[i] = Wout[i];
        w1[i] = Wout[D_H3 + i];
    }
    __syncthreads();

    const int warp = threadIdx.x >> 5, lane = threadIdx.x & 31;
    const float b0 = bout[0], b1 = bout[1];
    const float* Pr_base = g_P;
    const float* Pl_base = g_P + (size_t)T_SEQ * D_H3;

    for (int p = blockIdx.x * 8 + warp; p < NPAIRS; p += gridDim.x * 8) {
        const float4* Pr = (const float4*)(Pr_base + (size_t)pair_r[p] * D_H3);
        const float4* Pl = (const float4*)(Pl_base + (size_t)pair_l[p] * D_H3);
        float a0 = 0.f, a1 = 0.f;
#pragma unroll 4
        for (int k4 = lane; k4 < D_H3 / 4; k4 += 32) {
            float4 r = __ldg(Pr + k4);
            float4 l = __ldg(Pl + k4);
            int kb = k4 << 2;
            float s0 = fmaxf(r.x + l.x, 0.f);
            float s1 = fmaxf(r.y + l.y, 0.f);
            float s2 = fmaxf(r.z + l.z, 0.f);
            float s3 = fmaxf(r.w + l.w, 0.f);
            a0 = fmaf(s0, w0[kb], a0);     a1 = fmaf(s0, w1[kb], a1);
            a0 = fmaf(s1, w0[kb + 1], a0); a1 = fmaf(s1, w1[kb + 1], a1);
            a0 = fmaf(s2, w0[kb + 2], a0); a1 = fmaf(s2, w1[kb + 2], a1);
            a0 = fmaf(s3, w0[kb + 3], a0); a1 = fmaf(s3, w1[kb + 3], a1);
        }
#pragma unroll
        for (int off = 16; off > 0; off >>= 1) {
            a0 += __shfl_down_sync(0xFFFFFFFFu, a0, off);
            a1 += __shfl_down_sync(0xFFFFFFFFu, a1, off);
        }
        if (lane == 0) {
            float l0 = a0 + b0, l1 = a1 + b1;
            float m = fmaxf(l0, l1);
            float lse = m + logf(expf(l0 - m) + expf(l1 - m));
            out[2 * p]     = l0 - lse;
            out[2 * p + 1] = l1 - lse;
        }
    }
}

// ---------------------------------------------------------------------------
// Host
// ---------------------------------------------------------------------------
extern "C" void kernel_launch(void* const* d_in, const int* in_sizes, int n_in,
                              void* d_out, int out_size)
{
    const float* v_r    = (const float*)d_in[0];
    const float* v_l    = (const float*)d_in[1];
    const int*   pair_r = (const int*)  d_in[2];
    const int*   pair_l = (const int*)  d_in[3];
    const float* Wih0   = (const float*)d_in[4];
    const float* Whh0   = (const float*)d_in[5];
    const float* bih0   = (const float*)d_in[6];
    const float* bhh0   = (const float*)d_in[7];
    const float* Wih1   = (const float*)d_in[8];
    const float* Whh1   = (const float*)d_in[9];
    const float* bih1   = (const float*)d_in[10];
    const float* bhh1   = (const float*)d_in[11];
    const float* W1     = (const float*)d_in[12];
    const float* b1     = (const float*)d_in[13];
    const float* W2     = (const float*)d_in[14];
    const float* b2     = (const float*)d_in[15];
    const float* W3     = (const float*)d_in[16];
    const float* b3     = (const float*)d_in[17];
    const float* Wout   = (const float*)d_in[18];
    const float* bout   = (const float*)d_in[19];
    float* out = (float*)d_out;

    float *PRE, *H0, *H1, *FC1, *ENC, *PT, *WS, *BS;
    cudaGetSymbolAddress((void**)&PRE, g_PRE);
    cudaGetSymbolAddress((void**)&H0,  g_h0);
    cudaGetSymbolAddress((void**)&H1,  g_h1);
    cudaGetSymbolAddress((void**)&FC1, g_fc1);
    cudaGetSymbolAddress((void**)&ENC, g_enc);
    cudaGetSymbolAddress((void**)&PT,  g_P);
    cudaGetSymbolAddress((void**)&WS,  g_Ws);
    cudaGetSymbolAddress((void**)&BS,  g_bs);

    // --- Probe cluster-16 support (pure host query, capture-safe) ---
    cudaFuncSetAttribute(lstm_cluster_kernel,
                         cudaFuncAttributeNonPortableClusterSizeAllowed, 1);
    cudaLaunchConfig_t cfg = {};
    cfg.gridDim  = dim3(64, 1, 1);
    cfg.blockDim = dim3(256, 1, 1);
    cudaLaunchAttribute attrs[1];
    attrs[0].id = cudaLaunchAttributeClusterDimension;
    attrs[0].val.clusterDim = {16, 1, 1};
    cfg.attrs = attrs;
    cfg.numAttrs = 1;
    int numClusters = 0;
    cudaError_t qe = cudaOccupancyMaxActiveClusters(
        &numClusters, lstm_cluster_kernel, &cfg);
    bool use_cluster = (qe == cudaSuccess && numClusters >= 4);
    if (!use_cluster) cudaGetLastError();   // clear sticky error

    // 1. Precomputes
    pre0_kernel<<<dim3(4, 128, 4), 256>>>(v_r, v_l, Wih0, bih0, bhh0);
    bsum_kernel<<<8, 256>>>(bih1, bhh1);

    // 2. LSTM layer 0
    if (use_cluster) {
        cudaLaunchKernelEx(&cfg, lstm_cluster_kernel,
                           (const float*)PRE, Whh0, H0);
    } else {
        init_sent_kernel<<<(2 * T_SEQ * 512 + 255) / 256, 256>>>();
        lstm_kernel<<<64, 256>>>(PRE, Whh0, H0);
    }

    // 3. Layer-1 input gates, batched over seq (z=4)
    gemm_kernel<<<dim3(GATES / 128, T_SEQ / 128, 4), 256>>>(
        H0, Wih1, BS, PRE, T_SEQ, GATES, 512, 1.f, 0,
        (long)T_SEQ * 512, (long)GATES * 512, (long)GATES,
        (long)T_SEQ * GATES, 2, 2);

    // 4. LSTM layer 1
    if (use_cluster) {
        cudaLaunchKernelEx(&cfg, lstm_cluster_kernel,
                           (const float*)PRE, Whh1, H1);
    } else {
        lstm_kernel<<<64, 256>>>(PRE, Whh1, H1);
    }

    // 5. MLP encoders, batched over chain (z=2)
    gemm_kernel<<<dim3(D_H1 / 128, T_SEQ / 128, 2), 256>>>(
        H1, W1, b1, FC1, T_SEQ, D_H1, 512, 1.f, 1,
        (long)T_SEQ * 512, 0, 0, (long)T_SEQ * D_H1, 1, 1);

    gemm_kernel<<<dim3(D_H2 / 128, T_SEQ / 128, 2), 256>>>(
        FC1, W2, b2, ENC, T_SEQ, D_H2, D_H1, 1.f, 1,
        (long)T_SEQ * D_H1, 0, 0, (long)T_SEQ * D_H2, 1, 1);

    ws_kernel<<<(D_H3 * D_H2 + 255) / 256, 256>>>(W3);

    // P = 0.5*(enc @ Ws^T + b3)
    gemm_kernel<<<dim3(D_H3 / 128, T_SEQ / 128, 2), 256>>>(
        ENC, WS, b3, PT, T_SEQ, D_H3, D_H2, 0.5f, 0,
        (long)T_SEQ * D_H2, 0, 0, (long)T_SEQ * D_H3, 1, 1);

    // 6. Pair gather + dot + log_softmax
    pair_kernel<<<2048, 256>>>(pair_r, pair_l, Wout, bout, out);
}